// round 1
// baseline (speedup 1.0000x reference)
#include <cuda_runtime.h>

#define B_    32
#define IC    512
#define OC    512
#define HH    64
#define WW    64
#define WDIM  512
#define KTOT  (IC * 9)        // 4608
#define NTOT  (B_ * HH * WW)  // 131072

#define BM 128
#define BN 128
#define BK 16

// Scratch (no allocations allowed in kernel_launch)
__device__ float g_style[B_ * IC];   // style[b,i]
__device__ float g_cs[OC * IC];      // s_conv^2 * sum_k conv_w[o,i,k]^2
__device__ float g_f[B_ * OC];       // s_conv * rsqrt(t + 1e-8)

// ---------------------------------------------------------------------------
// style[b,i] = (w[b,:] . lin_w[i,:]) * sqrt(2/512) + lin_b[i]
// sqrt(2/512) = 1/16 exactly
// ---------------------------------------------------------------------------
__global__ void style_kernel(const float* __restrict__ w,
                             const float* __restrict__ lin_w,
                             const float* __restrict__ lin_b) {
    __shared__ float ws[WDIM];
    const int b = blockIdx.x;
    const int i = threadIdx.x;
    ws[i] = w[b * WDIM + i];
    __syncthreads();
    const float* lw = lin_w + (size_t)i * WDIM;
    float acc = 0.f;
#pragma unroll 8
    for (int d = 0; d < WDIM; d++) acc += ws[d] * lw[d];
    g_style[b * IC + i] = acc * 0.0625f + lin_b[i];
}

// ---------------------------------------------------------------------------
// cs[o,i] = (2/4608) * sum_k conv_w[o,i,k]^2   (2/4608 = 1/2304)
// ---------------------------------------------------------------------------
__global__ void cs_kernel(const float* __restrict__ conv_w) {
    const int idx = blockIdx.x * blockDim.x + threadIdx.x; // o*IC + i
    const float* p = conv_w + (size_t)idx * 9;
    float s = 0.f;
#pragma unroll
    for (int k = 0; k < 9; k++) { float v = p[k]; s += v * v; }
    g_cs[idx] = s * (1.0f / 2304.0f);
}

// ---------------------------------------------------------------------------
// f[b,o] = s_conv * rsqrt( sum_i style[b,i]^2 * cs[o,i] + 1e-8 )
// s_conv = sqrt(2/4608) = 1/48
// ---------------------------------------------------------------------------
__global__ void f_kernel() {
    __shared__ float st2[IC];
    const int b = blockIdx.x;
    const int o = threadIdx.x;
    float sv = g_style[b * IC + o];
    st2[o] = sv * sv;
    __syncthreads();
    const float* cs = g_cs + (size_t)o * IC;
    float t = 0.f;
#pragma unroll 8
    for (int i = 0; i < IC; i++) t += st2[i] * cs[i];
    g_f[b * OC + o] = (1.0f / 48.0f) * rsqrtf(t + 1e-8f);
}

// ---------------------------------------------------------------------------
// Implicit-GEMM conv: C[o, n] = sum_k W[o,k] * X[k,n]
//   k = i*9 + kh*3 + kw ;  n = b*4096 + h*64 + w
//   W[o,k]  = conv_w[o][i][kh][kw]           (exactly row-major layout)
//   X[k,n]  = style[b,i] * x[b,i,h+kh-1,w+kw-1]  (0 outside)
// Epilogue: out = f[b,o]*C + bias[o] + noise_w[o]*noise
// Classic 128x128x16 fp32 SGEMM, double-buffered smem, 8x8 per thread.
// ---------------------------------------------------------------------------
__global__ __launch_bounds__(256, 2)
void conv_kernel(const float* __restrict__ x, const float* __restrict__ cw,
                 const float* __restrict__ bias, const float* __restrict__ noise_w,
                 const float* __restrict__ noise, float* __restrict__ out) {
    __shared__ float As[2][BK][BM];
    __shared__ float Bs[2][BK][BN];

    const int t   = threadIdx.x;
    const int m0  = blockIdx.y * BM;
    const int n0  = blockIdx.x * BN;
    const int b   = n0 >> 12;          // 4096 spatial positions per image
    const int hw0 = n0 & 4095;         // tile stays within one image
    const int tx  = t & 15, ty = t >> 4;

    const float* stb = g_style + b * IC;
    const float* xb0 = x + (size_t)b * IC * 4096;

    // A loader: 2 x float4 per thread (128x16 tile)
    const int aRow0 = t >> 2;
    const int aC0   = (t & 3) * 4;
    const int aRow1 = aRow0 + 64;
    // B loader: one k-row (16 rows), 8 contiguous n per thread
    const int bkl = t >> 4;
    const int bn  = (t & 15) * 8;

    float4 aP0, aP1;
    float  bP[8];
    float  acc[8][8];
#pragma unroll
    for (int i = 0; i < 8; i++)
#pragma unroll
        for (int j = 0; j < 8; j++) acc[i][j] = 0.f;

#define FETCH(k0)                                                              \
    do {                                                                       \
        aP0 = *reinterpret_cast<const float4*>(                                \
            cw + (size_t)(m0 + aRow0) * KTOT + (k0) + aC0);                    \
        aP1 = *reinterpret_cast<const float4*>(                                \
            cw + (size_t)(m0 + aRow1) * KTOT + (k0) + aC0);                    \
        {                                                                      \
            int k  = (k0) + bkl;                                               \
            int i_ = k / 9;                                                    \
            int r  = k - i_ * 9;                                               \
            int kh = r / 3;                                                    \
            int kw = r - kh * 3;                                               \
            float sv = stb[i_];                                                \
            const float* xb = xb0 + (size_t)i_ * 4096;                         \
            int dh = kh - 1, dw = kw - 1;                                      \
            _Pragma("unroll")                                                  \
            for (int j = 0; j < 8; j++) {                                      \
                int hw = hw0 + bn + j;                                         \
                int h  = hw >> 6, wq = hw & 63;                                \
                int hp = h + dh, wp = wq + dw;                                 \
                float v = 0.f;                                                 \
                if ((unsigned)hp < 64u && (unsigned)wp < 64u)                  \
                    v = __ldg(xb + hp * 64 + wp) * sv;                         \
                bP[j] = v;                                                     \
            }                                                                  \
        }                                                                      \
    } while (0)

#define STORE(bf)                                                              \
    do {                                                                       \
        As[bf][aC0 + 0][aRow0] = aP0.x;                                        \
        As[bf][aC0 + 1][aRow0] = aP0.y;                                        \
        As[bf][aC0 + 2][aRow0] = aP0.z;                                        \
        As[bf][aC0 + 3][aRow0] = aP0.w;                                        \
        As[bf][aC0 + 0][aRow1] = aP1.x;                                        \
        As[bf][aC0 + 1][aRow1] = aP1.y;                                        \
        As[bf][aC0 + 2][aRow1] = aP1.z;                                        \
        As[bf][aC0 + 3][aRow1] = aP1.w;                                        \
        _Pragma("unroll")                                                      \
        for (int j = 0; j < 8; j++) Bs[bf][bkl][bn + j] = bP[j];               \
    } while (0)

    FETCH(0);
    STORE(0);
    __syncthreads();

    const int ntile = KTOT / BK;  // 288
    int buf = 0;
    for (int kt = 0; kt < ntile; kt++) {
        if (kt + 1 < ntile) FETCH((kt + 1) * BK);
#pragma unroll
        for (int kk = 0; kk < BK; kk++) {
            float a[8], bb[8];
            float4 a0 = *reinterpret_cast<const float4*>(&As[buf][kk][ty * 8]);
            float4 a1 = *reinterpret_cast<const float4*>(&As[buf][kk][ty * 8 + 4]);
            float4 b0 = *reinterpret_cast<const float4*>(&Bs[buf][kk][tx * 8]);
            float4 b1 = *reinterpret_cast<const float4*>(&Bs[buf][kk][tx * 8 + 4]);
            a[0] = a0.x; a[1] = a0.y; a[2] = a0.z; a[3] = a0.w;
            a[4] = a1.x; a[5] = a1.y; a[6] = a1.z; a[7] = a1.w;
            bb[0] = b0.x; bb[1] = b0.y; bb[2] = b0.z; bb[3] = b0.w;
            bb[4] = b1.x; bb[5] = b1.y; bb[6] = b1.z; bb[7] = b1.w;
#pragma unroll
            for (int im = 0; im < 8; im++)
#pragma unroll
                for (int in = 0; in < 8; in++)
                    acc[im][in] = fmaf(a[im], bb[in], acc[im][in]);
        }
        if (kt + 1 < ntile) {
            STORE(buf ^ 1);
            __syncthreads();
            buf ^= 1;
        }
    }

    // Epilogue: out = f[b,o]*acc + bias[o] + noise_w[o]*noise
    const int hwb = hw0 + tx * 8;
#pragma unroll
    for (int im = 0; im < 8; im++) {
        const int o  = m0 + ty * 8 + im;
        const float fo = g_f[b * OC + o];
        const float bo = bias[o];
        const float nw = noise_w[o];
        const size_t base = ((size_t)b * OC + o) * 4096 + hwb;
        float4 nv0 = *reinterpret_cast<const float4*>(noise + base);
        float4 nv1 = *reinterpret_cast<const float4*>(noise + base + 4);
        float4 o0, o1;
        o0.x = fmaf(acc[im][0], fo, fmaf(nw, nv0.x, bo));
        o0.y = fmaf(acc[im][1], fo, fmaf(nw, nv0.y, bo));
        o0.z = fmaf(acc[im][2], fo, fmaf(nw, nv0.z, bo));
        o0.w = fmaf(acc[im][3], fo, fmaf(nw, nv0.w, bo));
        o1.x = fmaf(acc[im][4], fo, fmaf(nw, nv1.x, bo));
        o1.y = fmaf(acc[im][5], fo, fmaf(nw, nv1.y, bo));
        o1.z = fmaf(acc[im][6], fo, fmaf(nw, nv1.z, bo));
        o1.w = fmaf(acc[im][7], fo, fmaf(nw, nv1.w, bo));
        *reinterpret_cast<float4*>(out + base)     = o0;
        *reinterpret_cast<float4*>(out + base + 4) = o1;
    }
#undef FETCH
#undef STORE
}

extern "C" void kernel_launch(void* const* d_in, const int* in_sizes, int n_in,
                              void* d_out, int out_size) {
    const float* x       = (const float*)d_in[0];
    const float* w       = (const float*)d_in[1];
    const float* conv_w  = (const float*)d_in[2];
    const float* lin_w   = (const float*)d_in[3];
    const float* lin_b   = (const float*)d_in[4];
    const float* bias    = (const float*)d_in[5];
    const float* noise_w = (const float*)d_in[6];
    const float* noise   = (const float*)d_in[7];
    float* out = (float*)d_out;

    style_kernel<<<B_, 512>>>(w, lin_w, lin_b);
    cs_kernel<<<(OC * IC) / 256, 256>>>(conv_w);
    f_kernel<<<B_, 512>>>();
    conv_kernel<<<dim3(NTOT / BN, OC / BM), 256>>>(x, conv_w, bias, noise_w,
                                                   noise, out);
}

// round 5
// speedup vs baseline: 7.2045x; 7.2045x over previous
#include <cuda_runtime.h>
#include <cstdint>

#define B_    32
#define IC    512
#define OC    512
#define WDIM  512

// ---------------------------------------------------------------------------
// Helpers (base-target PTX only: cp.async + mma.sync, no tcgen05/TMA)
// ---------------------------------------------------------------------------
__device__ __forceinline__ uint32_t smem_to_u32(const void* p) {
    uint32_t a;
    asm("{ .reg .u64 t; cvta.to.shared.u64 t, %1; cvt.u32.u64 %0, t; }"
        : "=r"(a) : "l"(p));
    return a;
}

__device__ __forceinline__ void cp_async16(uint32_t s, const void* g) {
    asm volatile("cp.async.cg.shared.global [%0], [%1], 16;" :: "r"(s), "l"(g));
}
__device__ __forceinline__ void cp_commit() {
    asm volatile("cp.async.commit_group;");
}
__device__ __forceinline__ void cp_wait1() {
    asm volatile("cp.async.wait_group 1;" ::: "memory");
}
__device__ __forceinline__ void cp_wait0() {
    asm volatile("cp.async.wait_group 0;" ::: "memory");
}

__device__ __forceinline__ void mma_tf32(float* d, const uint32_t* a,
                                         const uint32_t* b) {
    asm volatile(
        "mma.sync.aligned.m16n8k8.row.col.f32.tf32.tf32.f32 "
        "{%0,%1,%2,%3}, {%4,%5,%6,%7}, {%8,%9}, {%0,%1,%2,%3};"
        : "+f"(d[0]), "+f"(d[1]), "+f"(d[2]), "+f"(d[3])
        : "r"(a[0]), "r"(a[1]), "r"(a[2]), "r"(a[3]), "r"(b[0]), "r"(b[1]));
}

__device__ __forceinline__ float rna_tf32(float v) {
    asm("cvt.rna.tf32.f32 %0, %1;" : "=f"(v) : "f"(v));
    return v;
}

// ---------------------------------------------------------------------------
// Scratch
// ---------------------------------------------------------------------------
__device__ float g_style[B_ * IC];                 // style[b,i]
__device__ float g_cs[OC * IC];                    // s_conv^2 * sum_k cw^2
__device__ float g_f[B_ * OC];                     // demod factor
__device__ float g_cwr[9 * OC * IC];               // [s][o][i]  tf32-rounded
__device__ float g_xsp[(size_t)B_ * 66 * 66 * IC]; // [b][h][w][i] padded, tf32

// ---------------------------------------------------------------------------
// Prep kernels
// ---------------------------------------------------------------------------
__global__ void style_kernel(const float* __restrict__ w,
                             const float* __restrict__ lin_w,
                             const float* __restrict__ lin_b) {
    __shared__ float ws[WDIM];
    const int b = blockIdx.x;
    const int i = threadIdx.x;
    ws[i] = w[b * WDIM + i];
    __syncthreads();
    const float* lw = lin_w + (size_t)i * WDIM;
    float acc = 0.f;
#pragma unroll 8
    for (int d = 0; d < WDIM; d++) acc += ws[d] * lw[d];
    g_style[b * IC + i] = acc * 0.0625f + lin_b[i];
}

__global__ void cs_kernel(const float* __restrict__ conv_w) {
    const int idx = blockIdx.x * blockDim.x + threadIdx.x;
    const float* p = conv_w + (size_t)idx * 9;
    float s = 0.f;
#pragma unroll
    for (int k = 0; k < 9; k++) { float v = p[k]; s += v * v; }
    g_cs[idx] = s * (1.0f / 2304.0f);
}

__global__ void f_kernel() {
    __shared__ float st2[IC];
    const int b = blockIdx.x;
    const int o = threadIdx.x;
    float sv = g_style[b * IC + o];
    st2[o] = sv * sv;
    __syncthreads();
    const float* cs = g_cs + (size_t)o * IC;
    float t = 0.f;
#pragma unroll 8
    for (int i = 0; i < IC; i++) t += st2[i] * cs[i];
    g_f[b * OC + o] = (1.0f / 48.0f) * rsqrtf(t + 1e-8f);
}

// cwr[s][o][i] = rna_tf32(conv_w[o][i][s])
__global__ void cwr_kernel(const float* __restrict__ cw) {
    const int j = blockIdx.x * 256 + threadIdx.x;
    const int s = j >> 18;
    const int rem = j & 262143;
    const int o = rem >> 9, i = rem & 511;
    g_cwr[j] = rna_tf32(cw[(size_t)(o * IC + i) * 9 + s]);
}

// zero the padded border of g_xsp
__global__ void border_kernel() {
    const int idx = blockIdx.x * 256 + threadIdx.x;  // 32*260*512 threads
    const int i = idx & 511;
    const int p = idx >> 9;
    const int b = p / 260;
    const int r = p - b * 260;
    int h, w;
    if (r < 66)       { h = 0;  w = r; }
    else if (r < 132) { h = 65; w = r - 66; }
    else { int r2 = r - 132; h = 1 + (r2 >> 1); w = (r2 & 1) * 65; }
    g_xsp[((size_t)(b * 66 + h) * 66 + w) * IC + i] = 0.f;
}

// xsp[b][h+1][w+1][i] = rna_tf32(x[b][i][h][w] * style[b][i])
__global__ void xsp_kernel(const float* __restrict__ x) {
    __shared__ float sm[64][65];
    const int bh = blockIdx.x;
    const int b = bh >> 6, h = bh & 63;
    const int tx = threadIdx.x & 63, ty = threadIdx.x >> 6;  // 256 threads
    for (int ic = 0; ic < 8; ic++) {
#pragma unroll
        for (int r = 0; r < 16; r++) {
            const int il = ty + r * 4;
            const int i = ic * 64 + il;
            float v = x[((size_t)(b * IC) + i) * 4096 + h * 64 + tx] *
                      g_style[b * IC + i];
            sm[il][tx] = rna_tf32(v);
        }
        __syncthreads();
#pragma unroll
        for (int r = 0; r < 16; r++) {
            const int w = ty + r * 4;
            g_xsp[((size_t)(b * 66 + h + 1) * 66 + (w + 1)) * IC + ic * 64 + tx] =
                sm[tx][w];
        }
        __syncthreads();
    }
}

// ---------------------------------------------------------------------------
// Main GEMM kernel: tf32 mma.sync, 128x128x32 CTA, cp.async double buffer.
//   C[o,n] = sum over 9 shifts s, 512 channels i of cwr[s][o][i]*xsp[...shift][i]
//   Epilogue: out = f[b,o]*C + bias[o] + noise_w[o]*noise
// Warp layout: 8 warps = 2 (M) x 4 (N); warp tile 64x32; m16n8k8 frags.
// SMEM tiles [row][32] floats, elem swizzle col ^ ((row&7)<<2) -> conflict-free.
// ---------------------------------------------------------------------------
#define STAGE_FLOATS 8192          // A 128*32 + B 128*32
#define GEMM_SMEM    (2 * STAGE_FLOATS * 4)

__global__ void __launch_bounds__(256, 2)
conv_mma_kernel(const float* __restrict__ bias, const float* __restrict__ noise_w,
                const float* __restrict__ noise, float* __restrict__ out) {
    extern __shared__ float smf[];
    const uint32_t sb = smem_to_u32(smf);

    const int t   = threadIdx.x;
    const int wid = t >> 5, lid = t & 31;
    const int m0  = blockIdx.y * 128;
    const int nt  = blockIdx.x;          // 0..1023
    const int b   = nt >> 5;
    const int h0  = (nt & 31) * 2;       // 2 output rows per tile
    const int hw0 = (nt & 31) * 128;

    const int wm = wid >> 2, wn = wid & 3;
    const int mBase = wm * 64, nBase = wn * 32;
    const int r = lid >> 2, cq = lid & 3;

    // loader indices: 4 float4 per tile per thread
    const int lrow0 = t >> 3;            // 0..31 (+32 per iter)
    const int lchk  = t & 7;             // 16B chunk in a 128B row

    float acc[4][4][4];
#pragma unroll
    for (int a = 0; a < 4; a++)
#pragma unroll
        for (int bq = 0; bq < 4; bq++)
#pragma unroll
            for (int cc = 0; cc < 4; cc++) acc[a][bq][cc] = 0.f;

#define LOAD_STAGE(c_, stg_)                                                    \
    do {                                                                        \
        const int s_  = (c_) >> 4;                                              \
        const int kc_ = (c_) & 15;                                              \
        const int kh_ = s_ / 3, kw_ = s_ - kh_ * 3;                             \
        const uint32_t aBase = sb + (stg_) * (STAGE_FLOATS * 4);                \
        const uint32_t bBase = aBase + 128 * 32 * 4;                            \
        const float* Ag = g_cwr + ((size_t)(s_ * OC + m0) * IC) + kc_ * 32 +    \
                          lchk * 4;                                             \
        _Pragma("unroll")                                                       \
        for (int it = 0; it < 4; it++) {                                        \
            const int row = lrow0 + it * 32;                                    \
            const uint32_t dst = aBase +                                        \
                (row * 32 + ((lchk * 4) ^ ((row & 7) << 2))) * 4;               \
            cp_async16(dst, Ag + (size_t)row * IC);                             \
        }                                                                       \
        _Pragma("unroll")                                                       \
        for (int it = 0; it < 4; it++) {                                        \
            const int row = lrow0 + it * 32;                                    \
            const int hg = h0 + (row >> 6) + kh_;                               \
            const int wg = (row & 63) + kw_;                                    \
            const float* Bg = g_xsp +                                           \
                ((size_t)((b * 66 + hg) * 66 + wg)) * IC + kc_ * 32 + lchk * 4; \
            const uint32_t dst = bBase +                                        \
                (row * 32 + ((lchk * 4) ^ ((row & 7) << 2))) * 4;               \
            cp_async16(dst, Bg);                                                \
        }                                                                       \
        cp_commit();                                                            \
    } while (0)

    LOAD_STAGE(0, 0);

    int stg = 0;
    for (int c = 0; c < 144; c++) {
        if (c + 1 < 144) {
            LOAD_STAGE(c + 1, stg ^ 1);
            cp_wait1();
        } else {
            cp_wait0();
        }
        __syncthreads();

        const float* As = smf + stg * STAGE_FLOATS;
        const float* Bs = As + 128 * 32;
#pragma unroll
        for (int ks = 0; ks < 4; ks++) {
            const int k0 = ks * 8;
            uint32_t af[4][4], bf[4][2];
#pragma unroll
            for (int mi = 0; mi < 4; mi++) {
                const int mrow = mBase + mi * 16 + r;
                const int sw = (mrow & 7) << 2;
                const float* A0 = As + mrow * 32;
                const float* A1 = As + (mrow + 8) * 32;
                af[mi][0] = __float_as_uint(A0[(k0 + cq) ^ sw]);
                af[mi][1] = __float_as_uint(A1[(k0 + cq) ^ sw]);
                af[mi][2] = __float_as_uint(A0[(k0 + cq + 4) ^ sw]);
                af[mi][3] = __float_as_uint(A1[(k0 + cq + 4) ^ sw]);
            }
#pragma unroll
            for (int ni = 0; ni < 4; ni++) {
                const int nrow = nBase + ni * 8 + r;
                const int sw = (nrow & 7) << 2;
                const float* Bp = Bs + nrow * 32;
                bf[ni][0] = __float_as_uint(Bp[(k0 + cq) ^ sw]);
                bf[ni][1] = __float_as_uint(Bp[(k0 + cq + 4) ^ sw]);
            }
#pragma unroll
            for (int mi = 0; mi < 4; mi++)
#pragma unroll
                for (int ni = 0; ni < 4; ni++)
                    mma_tf32(acc[mi][ni], af[mi], bf[ni]);
        }
        __syncthreads();
        stg ^= 1;
    }
#undef LOAD_STAGE

    // Epilogue: out = f[b,o]*acc + bias[o] + noise_w[o]*noise
#pragma unroll
    for (int mi = 0; mi < 4; mi++) {
#pragma unroll
        for (int half = 0; half < 2; half++) {
            const int o = m0 + mBase + mi * 16 + r + half * 8;
            const float fo = g_f[b * OC + o];
            const float bo = bias[o];
            const float nw = noise_w[o];
            const size_t base = ((size_t)b * OC + o) * 4096 + hw0 + nBase;
#pragma unroll
            for (int ni = 0; ni < 4; ni++) {
                const size_t off = base + ni * 8 + cq * 2;
                float2 nv = *reinterpret_cast<const float2*>(noise + off);
                const float d0 = acc[mi][ni][half * 2 + 0];
                const float d1 = acc[mi][ni][half * 2 + 1];
                float2 ov;
                ov.x = fmaf(fo, d0, fmaf(nw, nv.x, bo));
                ov.y = fmaf(fo, d1, fmaf(nw, nv.y, bo));
                *reinterpret_cast<float2*>(out + off) = ov;
            }
        }
    }
}

// ---------------------------------------------------------------------------
extern "C" void kernel_launch(void* const* d_in, const int* in_sizes, int n_in,
                              void* d_out, int out_size) {
    const float* x       = (const float*)d_in[0];
    const float* w       = (const float*)d_in[1];
    const float* conv_w  = (const float*)d_in[2];
    const float* lin_w   = (const float*)d_in[3];
    const float* lin_b   = (const float*)d_in[4];
    const float* bias    = (const float*)d_in[5];
    const float* noise_w = (const float*)d_in[6];
    const float* noise   = (const float*)d_in[7];
    float* out = (float*)d_out;

    style_kernel<<<B_, 512>>>(w, lin_w, lin_b);
    cwr_kernel<<<(9 * OC * IC) / 256, 256>>>(conv_w);
    cs_kernel<<<(OC * IC) / 256, 256>>>(conv_w);
    f_kernel<<<B_, 512>>>();
    border_kernel<<<(32 * 260 * 512) / 256, 256>>>();
    xsp_kernel<<<B_ * 64, 256>>>(x);

    cudaFuncSetAttribute(conv_mma_kernel,
                         cudaFuncAttributeMaxDynamicSharedMemorySize, GEMM_SMEM);
    conv_mma_kernel<<<dim3(1024, 4), 256, GEMM_SMEM>>>(bias, noise_w, noise, out);
}

// round 6
// speedup vs baseline: 7.7458x; 1.0751x over previous
#include <cuda_runtime.h>
#include <cstdint>

#define B_    32
#define IC    512
#define OC    512
#define WDIM  512

// ---------------------------------------------------------------------------
// Helpers (base-target PTX only: cp.async + mma.sync, no tcgen05/TMA)
// ---------------------------------------------------------------------------
__device__ __forceinline__ uint32_t smem_to_u32(const void* p) {
    uint32_t a;
    asm("{ .reg .u64 t; cvta.to.shared.u64 t, %1; cvt.u32.u64 %0, t; }"
        : "=r"(a) : "l"(p));
    return a;
}

__device__ __forceinline__ void cp_async16(uint32_t s, const void* g) {
    asm volatile("cp.async.cg.shared.global [%0], [%1], 16;" :: "r"(s), "l"(g));
}
__device__ __forceinline__ void cp_commit() {
    asm volatile("cp.async.commit_group;");
}
__device__ __forceinline__ void cp_wait1() {
    asm volatile("cp.async.wait_group 1;" ::: "memory");
}
__device__ __forceinline__ void cp_wait0() {
    asm volatile("cp.async.wait_group 0;" ::: "memory");
}

__device__ __forceinline__ void mma_tf32(float* d, const uint32_t* a,
                                         const uint32_t* b) {
    asm volatile(
        "mma.sync.aligned.m16n8k8.row.col.f32.tf32.tf32.f32 "
        "{%0,%1,%2,%3}, {%4,%5,%6,%7}, {%8,%9}, {%0,%1,%2,%3};"
        : "+f"(d[0]), "+f"(d[1]), "+f"(d[2]), "+f"(d[3])
        : "r"(a[0]), "r"(a[1]), "r"(a[2]), "r"(a[3]), "r"(b[0]), "r"(b[1]));
}

__device__ __forceinline__ float rna_tf32(float v) {
    asm("cvt.rna.tf32.f32 %0, %1;" : "=f"(v) : "f"(v));
    return v;
}

// ---------------------------------------------------------------------------
// Scratch
// ---------------------------------------------------------------------------
__device__ float g_style[B_ * IC];                 // style[b,i]
__device__ float g_cs[OC * IC];                    // s_conv^2 * sum_k cw^2
__device__ float g_f[B_ * OC];                     // demod factor
__device__ float g_cwr[9 * OC * IC];               // [s][o][i]  tf32-rounded
__device__ float g_xsp[(size_t)B_ * 66 * 66 * IC]; // [b][h][w][i] padded, tf32

// ---------------------------------------------------------------------------
// Prep kernels
// ---------------------------------------------------------------------------
// style[b,i] = (w[b,:] . lin_w[i,:]) / 16 + lin_b[i]
// one warp per (b,i): 16384 warps
__global__ void style_kernel(const float* __restrict__ w,
                             const float* __restrict__ lin_w,
                             const float* __restrict__ lin_b) {
    const int gw  = (blockIdx.x * 256 + threadIdx.x) >> 5;  // global warp
    const int lid = threadIdx.x & 31;
    const int b = gw >> 9, i = gw & 511;
    const float* wr = w + b * WDIM;
    const float* lw = lin_w + (size_t)i * WDIM;
    float acc = 0.f;
#pragma unroll
    for (int d = 0; d < WDIM / 32; d++)
        acc += wr[d * 32 + lid] * lw[d * 32 + lid];
#pragma unroll
    for (int off = 16; off > 0; off >>= 1)
        acc += __shfl_xor_sync(0xffffffffu, acc, off);
    if (lid == 0) g_style[b * IC + i] = acc * 0.0625f + lin_b[i];
}

__global__ void cs_kernel(const float* __restrict__ conv_w) {
    const int idx = blockIdx.x * blockDim.x + threadIdx.x;
    const float* p = conv_w + (size_t)idx * 9;
    float s = 0.f;
#pragma unroll
    for (int k = 0; k < 9; k++) { float v = p[k]; s += v * v; }
    g_cs[idx] = s * (1.0f / 2304.0f);
}

// f[b,o] = (1/48) * rsqrt( sum_i style[b,i]^2 * cs[o,i] + 1e-8 )
// one warp per (b,o): 16384 warps
__global__ void f_kernel() {
    const int gw  = (blockIdx.x * 256 + threadIdx.x) >> 5;
    const int lid = threadIdx.x & 31;
    const int b = gw >> 9, o = gw & 511;
    const float* st = g_style + b * IC;
    const float* cs = g_cs + (size_t)o * IC;
    float acc = 0.f;
#pragma unroll
    for (int d = 0; d < IC / 32; d++) {
        float sv = st[d * 32 + lid];
        acc += sv * sv * cs[d * 32 + lid];
    }
#pragma unroll
    for (int off = 16; off > 0; off >>= 1)
        acc += __shfl_xor_sync(0xffffffffu, acc, off);
    if (lid == 0) g_f[b * OC + o] = (1.0f / 48.0f) * rsqrtf(acc + 1e-8f);
}

// cwr[s][o][i] = rna_tf32(conv_w[o][i][s])
__global__ void cwr_kernel(const float* __restrict__ cw) {
    const int j = blockIdx.x * 256 + threadIdx.x;
    const int s = j >> 18;
    const int rem = j & 262143;
    const int o = rem >> 9, i = rem & 511;
    g_cwr[j] = rna_tf32(cw[(size_t)(o * IC + i) * 9 + s]);
}

// zero the padded border of g_xsp
__global__ void border_kernel() {
    const int idx = blockIdx.x * 256 + threadIdx.x;  // 32*260*512 threads
    const int i = idx & 511;
    const int p = idx >> 9;
    const int b = p / 260;
    const int r = p - b * 260;
    int h, w;
    if (r < 66)       { h = 0;  w = r; }
    else if (r < 132) { h = 65; w = r - 66; }
    else { int r2 = r - 132; h = 1 + (r2 >> 1); w = (r2 & 1) * 65; }
    g_xsp[((size_t)(b * 66 + h) * 66 + w) * IC + i] = 0.f;
}

// xsp[b][h+1][w+1][i] = rna_tf32(x[b][i][h][w] * style[b][i])
__global__ void xsp_kernel(const float* __restrict__ x) {
    __shared__ float sm[64][65];
    const int bh = blockIdx.x;
    const int b = bh >> 6, h = bh & 63;
    const int tx = threadIdx.x & 63, ty = threadIdx.x >> 6;  // 256 threads
    for (int ic = 0; ic < 8; ic++) {
#pragma unroll
        for (int r = 0; r < 16; r++) {
            const int il = ty + r * 4;
            const int i = ic * 64 + il;
            float v = x[((size_t)(b * IC) + i) * 4096 + h * 64 + tx] *
                      g_style[b * IC + i];
            sm[il][tx] = rna_tf32(v);
        }
        __syncthreads();
#pragma unroll
        for (int r = 0; r < 16; r++) {
            const int w = ty + r * 4;
            g_xsp[((size_t)(b * 66 + h + 1) * 66 + (w + 1)) * IC + ic * 64 + tx] =
                sm[tx][w];
        }
        __syncthreads();
    }
}

// ---------------------------------------------------------------------------
// Main GEMM kernel: tf32 mma.sync, 128x128x32 CTA, cp.async 3-stage ring.
//   C[o,n] = sum over 9 shifts s, 512 channels i of cwr[s][o][i]*xsp[...shift][i]
//   Epilogue: out = f[b,o]*C + bias[o] + noise_w[o]*noise
// Warp layout: 8 warps = 2 (M) x 4 (N); warp tile 64x32; m16n8k8 frags.
// SMEM tiles [row][32] floats, elem swizzle col ^ ((row&7)<<2) -> conflict-free.
// 3 stages, ONE __syncthreads per k-chunk:
//   iter c:  wait(group c) ; sync ; issue(c+2) into (c+2)%3 ; compute(c%3)
// issue into (c+2)%3 == (c-1)%3 is safe: it is after sync(c), and every warp
// finished compute(c-1) before sync(c).
// ---------------------------------------------------------------------------
#define STAGE_FLOATS 8192          // A 128*32 + B 128*32
#define STAGES 3
#define GEMM_SMEM (STAGES * STAGE_FLOATS * 4)   // 96 KB

__global__ void __launch_bounds__(256, 2)
conv_mma_kernel(const float* __restrict__ bias, const float* __restrict__ noise_w,
                const float* __restrict__ noise, float* __restrict__ out) {
    extern __shared__ float smf[];
    const uint32_t sb = smem_to_u32(smf);

    const int t   = threadIdx.x;
    const int wid = t >> 5, lid = t & 31;
    const int m0  = blockIdx.x * 128;    // 4 m-blocks, fastest -> L2 B-sharing
    const int nt  = blockIdx.y;          // 0..1023
    const int b   = nt >> 5;
    const int h0  = (nt & 31) * 2;       // 2 output rows per tile
    const int hw0 = (nt & 31) * 128;

    const int wm = wid >> 2, wn = wid & 3;
    const int mBase = wm * 64, nBase = wn * 32;
    const int r = lid >> 2, cq = lid & 3;

    // loader indices: 4 float4 per tile per thread
    const int lrow0 = t >> 3;            // 0..31 (+32 per iter)
    const int lchk  = t & 7;             // 16B chunk in a 128B row

    float acc[4][4][4];
#pragma unroll
    for (int a = 0; a < 4; a++)
#pragma unroll
        for (int bq = 0; bq < 4; bq++)
#pragma unroll
            for (int cc = 0; cc < 4; cc++) acc[a][bq][cc] = 0.f;

#define LOAD_STAGE(c_, stg_)                                                    \
    do {                                                                        \
        const int s_  = (c_) >> 4;                                              \
        const int kc_ = (c_) & 15;                                              \
        const int kh_ = s_ / 3, kw_ = s_ - kh_ * 3;                             \
        const uint32_t aBase = sb + (stg_) * (STAGE_FLOATS * 4);                \
        const uint32_t bBase = aBase + 128 * 32 * 4;                            \
        const float* Ag = g_cwr + ((size_t)(s_ * OC + m0) * IC) + kc_ * 32 +    \
                          lchk * 4;                                             \
        _Pragma("unroll")                                                       \
        for (int it = 0; it < 4; it++) {                                        \
            const int row = lrow0 + it * 32;                                    \
            const uint32_t dst = aBase +                                        \
                (row * 32 + ((lchk * 4) ^ ((row & 7) << 2))) * 4;               \
            cp_async16(dst, Ag + (size_t)row * IC);                             \
        }                                                                       \
        _Pragma("unroll")                                                       \
        for (int it = 0; it < 4; it++) {                                        \
            const int row = lrow0 + it * 32;                                    \
            const int hg = h0 + (row >> 6) + kh_;                               \
            const int wg = (row & 63) + kw_;                                    \
            const float* Bg = g_xsp +                                           \
                ((size_t)((b * 66 + hg) * 66 + wg)) * IC + kc_ * 32 + lchk * 4; \
            const uint32_t dst = bBase +                                        \
                (row * 32 + ((lchk * 4) ^ ((row & 7) << 2))) * 4;               \
            cp_async16(dst, Bg);                                                \
        }                                                                       \
        cp_commit();                                                            \
    } while (0)

    LOAD_STAGE(0, 0);
    LOAD_STAGE(1, 1);

    int stg = 0;
    for (int c = 0; c < 144; c++) {
        if (c < 143) cp_wait1(); else cp_wait0();
        __syncthreads();
        if (c + 2 < 144) {
            const int stg2 = (stg + 2 >= STAGES) ? (stg + 2 - STAGES) : (stg + 2);
            LOAD_STAGE(c + 2, stg2);
        }

        const float* As = smf + stg * STAGE_FLOATS;
        const float* Bs = As + 128 * 32;
#pragma unroll
        for (int ks = 0; ks < 4; ks++) {
            const int k0 = ks * 8;
            uint32_t af[4][4], bf[4][2];
#pragma unroll
            for (int mi = 0; mi < 4; mi++) {
                const int mrow = mBase + mi * 16 + r;
                const int sw = (mrow & 7) << 2;
                const float* A0 = As + mrow * 32;
                const float* A1 = As + (mrow + 8) * 32;
                af[mi][0] = __float_as_uint(A0[(k0 + cq) ^ sw]);
                af[mi][1] = __float_as_uint(A1[(k0 + cq) ^ sw]);
                af[mi][2] = __float_as_uint(A0[(k0 + cq + 4) ^ sw]);
                af[mi][3] = __float_as_uint(A1[(k0 + cq + 4) ^ sw]);
            }
#pragma unroll
            for (int ni = 0; ni < 4; ni++) {
                const int nrow = nBase + ni * 8 + r;
                const int sw = (nrow & 7) << 2;
                const float* Bp = Bs + nrow * 32;
                bf[ni][0] = __float_as_uint(Bp[(k0 + cq) ^ sw]);
                bf[ni][1] = __float_as_uint(Bp[(k0 + cq + 4) ^ sw]);
            }
#pragma unroll
            for (int mi = 0; mi < 4; mi++)
#pragma unroll
                for (int ni = 0; ni < 4; ni++)
                    mma_tf32(acc[mi][ni], af[mi], bf[ni]);
        }
        stg = (stg + 1 >= STAGES) ? 0 : (stg + 1);
    }
#undef LOAD_STAGE

    // Epilogue: out = f[b,o]*acc + bias[o] + noise_w[o]*noise
#pragma unroll
    for (int mi = 0; mi < 4; mi++) {
#pragma unroll
        for (int half = 0; half < 2; half++) {
            const int o = m0 + mBase + mi * 16 + r + half * 8;
            const float fo = g_f[b * OC + o];
            const float bo = bias[o];
            const float nw = noise_w[o];
            const size_t base = ((size_t)b * OC + o) * 4096 + hw0 + nBase;
#pragma unroll
            for (int ni = 0; ni < 4; ni++) {
                const size_t off = base + ni * 8 + cq * 2;
                float2 nv = *reinterpret_cast<const float2*>(noise + off);
                const float d0 = acc[mi][ni][half * 2 + 0];
                const float d1 = acc[mi][ni][half * 2 + 1];
                float2 ov;
                ov.x = fmaf(fo, d0, fmaf(nw, nv.x, bo));
                ov.y = fmaf(fo, d1, fmaf(nw, nv.y, bo));
                *reinterpret_cast<float2*>(out + off) = ov;
            }
        }
    }
}

// ---------------------------------------------------------------------------
extern "C" void kernel_launch(void* const* d_in, const int* in_sizes, int n_in,
                              void* d_out, int out_size) {
    const float* x       = (const float*)d_in[0];
    const float* w       = (const float*)d_in[1];
    const float* conv_w  = (const float*)d_in[2];
    const float* lin_w   = (const float*)d_in[3];
    const float* lin_b   = (const float*)d_in[4];
    const float* bias    = (const float*)d_in[5];
    const float* noise_w = (const float*)d_in[6];
    const float* noise   = (const float*)d_in[7];
    float* out = (float*)d_out;

    style_kernel<<<(B_ * IC) / 8, 256>>>(w, lin_w, lin_b);
    cwr_kernel<<<(9 * OC * IC) / 256, 256>>>(conv_w);
    cs_kernel<<<(OC * IC) / 256, 256>>>(conv_w);
    f_kernel<<<(B_ * OC) / 8, 256>>>();
    border_kernel<<<(32 * 260 * 512) / 256, 256>>>();
    xsp_kernel<<<B_ * 64, 256>>>(x);

    cudaFuncSetAttribute(conv_mma_kernel,
                         cudaFuncAttributeMaxDynamicSharedMemorySize, GEMM_SMEM);
    conv_mma_kernel<<<dim3(4, 1024), 256, GEMM_SMEM>>>(bias, noise_w, noise, out);
}

// round 7
// speedup vs baseline: 8.5250x; 1.1006x over previous
#include <cuda_runtime.h>
#include <cstdint>

#define B_    32
#define IC    512
#define OC    512
#define WDIM  512

// ---------------------------------------------------------------------------
// Helpers (base-target PTX only: cp.async + mma.sync + ldmatrix)
// ---------------------------------------------------------------------------
__device__ __forceinline__ uint32_t smem_to_u32(const void* p) {
    uint32_t a;
    asm("{ .reg .u64 t; cvta.to.shared.u64 t, %1; cvt.u32.u64 %0, t; }"
        : "=r"(a) : "l"(p));
    return a;
}

__device__ __forceinline__ void cp_async16(uint32_t s, const void* g) {
    asm volatile("cp.async.cg.shared.global [%0], [%1], 16;" :: "r"(s), "l"(g));
}
__device__ __forceinline__ void cp_commit() {
    asm volatile("cp.async.commit_group;");
}
__device__ __forceinline__ void cp_wait1() {
    asm volatile("cp.async.wait_group 1;" ::: "memory");
}
__device__ __forceinline__ void cp_wait0() {
    asm volatile("cp.async.wait_group 0;" ::: "memory");
}

__device__ __forceinline__ void ldsm_x4(uint32_t* r, uint32_t addr) {
    asm volatile("ldmatrix.sync.aligned.m8n8.x4.shared.b16 {%0,%1,%2,%3}, [%4];"
                 : "=r"(r[0]), "=r"(r[1]), "=r"(r[2]), "=r"(r[3]) : "r"(addr));
}

__device__ __forceinline__ void mma_tf32(float* d, const uint32_t* a,
                                         const uint32_t b0, const uint32_t b1) {
    asm volatile(
        "mma.sync.aligned.m16n8k8.row.col.f32.tf32.tf32.f32 "
        "{%0,%1,%2,%3}, {%4,%5,%6,%7}, {%8,%9}, {%0,%1,%2,%3};"
        : "+f"(d[0]), "+f"(d[1]), "+f"(d[2]), "+f"(d[3])
        : "r"(a[0]), "r"(a[1]), "r"(a[2]), "r"(a[3]), "r"(b0), "r"(b1));
}

__device__ __forceinline__ float rna_tf32(float v) {
    asm("cvt.rna.tf32.f32 %0, %1;" : "=f"(v) : "f"(v));
    return v;
}

// ---------------------------------------------------------------------------
// Scratch
// ---------------------------------------------------------------------------
__device__ float g_style[B_ * IC];                 // style[b,i]
__device__ float g_cs[OC * IC];                    // s_conv^2 * sum_k cw^2
__device__ float g_f[B_ * OC];                     // demod factor
__device__ float g_cwr[9 * OC * IC];               // [s][o][i]  tf32-rounded
__device__ float g_xsp[(size_t)B_ * 66 * 66 * IC]; // [b][h][w][i] padded, tf32

// ---------------------------------------------------------------------------
// prep1: border zeroing + cwr relayout + cs reduction (independent jobs)
//   blocks [0, 16640)            -> border
//   blocks [16640, 16640+9216)   -> cwr
//   blocks [25856, 25856+1024)   -> cs
// ---------------------------------------------------------------------------
#define BORDER_BLKS 16640
#define CWR_BLKS    9216
#define CS_BLKS     1024

__global__ void prep1_kernel(const float* __restrict__ cw) {
    const int bid = blockIdx.x;
    if (bid < BORDER_BLKS) {
        const int idx = bid * 256 + threadIdx.x;      // 32*260*512
        const int i = idx & 511;
        const int p = idx >> 9;
        const int b = p / 260;
        const int r = p - b * 260;
        int h, w;
        if (r < 66)       { h = 0;  w = r; }
        else if (r < 132) { h = 65; w = r - 66; }
        else { int r2 = r - 132; h = 1 + (r2 >> 1); w = (r2 & 1) * 65; }
        g_xsp[((size_t)(b * 66 + h) * 66 + w) * IC + i] = 0.f;
    } else if (bid < BORDER_BLKS + CWR_BLKS) {
        const int j = (bid - BORDER_BLKS) * 256 + threadIdx.x;  // 9*512*512
        const int s = j >> 18;
        const int rem = j & 262143;
        const int o = rem >> 9, i = rem & 511;
        g_cwr[j] = rna_tf32(cw[(size_t)(o * IC + i) * 9 + s]);
    } else {
        const int idx = (bid - BORDER_BLKS - CWR_BLKS) * 256 + threadIdx.x;
        const float* p = cw + (size_t)idx * 9;
        float s = 0.f;
#pragma unroll
        for (int k = 0; k < 9; k++) { float v = p[k]; s += v * v; }
        g_cs[idx] = s * (1.0f / 2304.0f);
    }
}

// ---------------------------------------------------------------------------
// style[b,i] = (w[b,:] . lin_w[i,:]) / 16 + lin_b[i]   (one warp per (b,i))
// ---------------------------------------------------------------------------
__global__ void style_kernel(const float* __restrict__ w,
                             const float* __restrict__ lin_w,
                             const float* __restrict__ lin_b) {
    const int gw  = (blockIdx.x * 256 + threadIdx.x) >> 5;
    const int lid = threadIdx.x & 31;
    const int b = gw >> 9, i = gw & 511;
    const float* wr = w + b * WDIM;
    const float* lw = lin_w + (size_t)i * WDIM;
    float acc = 0.f;
#pragma unroll
    for (int d = 0; d < WDIM / 32; d++)
        acc += wr[d * 32 + lid] * lw[d * 32 + lid];
#pragma unroll
    for (int off = 16; off > 0; off >>= 1)
        acc += __shfl_xor_sync(0xffffffffu, acc, off);
    if (lid == 0) g_style[b * IC + i] = acc * 0.0625f + lin_b[i];
}

// ---------------------------------------------------------------------------
// prep3: xsp transpose+premultiply (blocks [0,2048)) + f demod (blocks [2048,4096))
// ---------------------------------------------------------------------------
__global__ void prep3_kernel(const float* __restrict__ x) {
    if (blockIdx.x < 2048) {
        __shared__ float sm[64][65];
        const int bh = blockIdx.x;
        const int b = bh >> 6, h = bh & 63;
        const int tx = threadIdx.x & 63, ty = threadIdx.x >> 6;
        for (int ic = 0; ic < 8; ic++) {
#pragma unroll
            for (int r = 0; r < 16; r++) {
                const int il = ty + r * 4;
                const int i = ic * 64 + il;
                float v = x[((size_t)(b * IC) + i) * 4096 + h * 64 + tx] *
                          g_style[b * IC + i];
                sm[il][tx] = rna_tf32(v);
            }
            __syncthreads();
#pragma unroll
            for (int r = 0; r < 16; r++) {
                const int w = ty + r * 4;
                g_xsp[((size_t)(b * 66 + h + 1) * 66 + (w + 1)) * IC + ic * 64 + tx] =
                    sm[tx][w];
            }
            __syncthreads();
        }
    } else {
        const int gw  = ((blockIdx.x - 2048) * 256 + threadIdx.x) >> 5;
        const int lid = threadIdx.x & 31;
        const int b = gw >> 9, o = gw & 511;
        const float* st = g_style + b * IC;
        const float* cs = g_cs + (size_t)o * IC;
        float acc = 0.f;
#pragma unroll
        for (int d = 0; d < IC / 32; d++) {
            float sv = st[d * 32 + lid];
            acc += sv * sv * cs[d * 32 + lid];
        }
#pragma unroll
        for (int off = 16; off > 0; off >>= 1)
            acc += __shfl_xor_sync(0xffffffffu, acc, off);
        if (lid == 0) g_f[b * OC + o] = (1.0f / 48.0f) * rsqrtf(acc + 1e-8f);
    }
}

// ---------------------------------------------------------------------------
// Main GEMM: tf32 mma.sync, 128x128x32 CTA, cp.async 3-stage ring, ldmatrix.
// ---------------------------------------------------------------------------
#define STAGE_FLOATS 8192          // A 128*32 + B 128*32
#define STAGES 3
#define GEMM_SMEM (STAGES * STAGE_FLOATS * 4)   // 96 KB

__global__ void __launch_bounds__(256, 2)
conv_mma_kernel(const float* __restrict__ bias, const float* __restrict__ noise_w,
                const float* __restrict__ noise, float* __restrict__ out) {
    extern __shared__ float smf[];
    const uint32_t sb = smem_to_u32(smf);

    const int t   = threadIdx.x;
    const int wid = t >> 5, lid = t & 31;
    const int m0  = blockIdx.x * 128;    // 4 m-blocks fastest -> L2 B-sharing
    const int nt  = blockIdx.y;          // 0..1023
    const int b   = nt >> 5;
    const int h0  = (nt & 31) * 2;
    const int hw0 = (nt & 31) * 128;

    const int wm = wid >> 2, wn = wid & 3;
    const int mBase = wm * 64, nBase = wn * 32;
    const int r = lid >> 2, cq = lid & 3;

    // ldmatrix addressing (per-thread constants)
    const int rowin = lid & 7;
    const uint32_t sww = (uint32_t)rowin << 2;        // swizzle xor (floats)
    const int jm = lid >> 3;                           // matrix index 0..3
    uint32_t aOff[4], bOff[2];
    {
        const int arb = mBase + ((jm & 1) << 3) + rowin;
#pragma unroll
        for (int mi = 0; mi < 4; mi++) aOff[mi] = (uint32_t)((arb + mi * 16) * 32) * 4u;
        const int brb = nBase + (((jm >> 1) & 1) << 3) + rowin;
        bOff[0] = (uint32_t)(brb * 32) * 4u;
        bOff[1] = (uint32_t)((brb + 16) * 32) * 4u;
    }
    const uint32_t hA = ((uint32_t)(lid >> 4) & 1u) << 2;   // A word-half select
    const uint32_t hB = ((uint32_t)(lid >> 3) & 1u) << 2;   // B word-half select

    // loader indices: 4 float4 per tile per thread
    const int lrow0 = t >> 3;
    const int lchk  = t & 7;

    float acc[4][4][4];
#pragma unroll
    for (int a = 0; a < 4; a++)
#pragma unroll
        for (int bq = 0; bq < 4; bq++)
#pragma unroll
            for (int cc = 0; cc < 4; cc++) acc[a][bq][cc] = 0.f;

#define LOAD_STAGE(c_, stg_)                                                    \
    do {                                                                        \
        const int s_  = (c_) >> 4;                                              \
        const int kc_ = (c_) & 15;                                              \
        const int kh_ = s_ / 3, kw_ = s_ - kh_ * 3;                             \
        const uint32_t aBase = sb + (stg_) * (STAGE_FLOATS * 4);                \
        const uint32_t bBase = aBase + 128 * 32 * 4;                            \
        const float* Ag = g_cwr + ((size_t)(s_ * OC + m0) * IC) + kc_ * 32 +    \
                          lchk * 4;                                             \
        _Pragma("unroll")                                                       \
        for (int it = 0; it < 4; it++) {                                        \
            const int row = lrow0 + it * 32;                                    \
            const uint32_t dst = aBase +                                        \
                (row * 32 + ((lchk * 4) ^ ((row & 7) << 2))) * 4;               \
            cp_async16(dst, Ag + (size_t)row * IC);                             \
        }                                                                       \
        _Pragma("unroll")                                                       \
        for (int it = 0; it < 4; it++) {                                        \
            const int row = lrow0 + it * 32;                                    \
            const int hg = h0 + (row >> 6) + kh_;                               \
            const int wg = (row & 63) + kw_;                                    \
            const float* Bg = g_xsp +                                           \
                ((size_t)((b * 66 + hg) * 66 + wg)) * IC + kc_ * 32 + lchk * 4; \
            const uint32_t dst = bBase +                                        \
                (row * 32 + ((lchk * 4) ^ ((row & 7) << 2))) * 4;               \
            cp_async16(dst, Bg);                                                \
        }                                                                       \
        cp_commit();                                                            \
    } while (0)

    LOAD_STAGE(0, 0);
    LOAD_STAGE(1, 1);

    int stg = 0;
    for (int c = 0; c < 144; c++) {
        if (c < 143) cp_wait1(); else cp_wait0();
        __syncthreads();
        if (c + 2 < 144) {
            const int stg2 = (stg + 2 >= STAGES) ? (stg + 2 - STAGES) : (stg + 2);
            LOAD_STAGE(c + 2, stg2);
        }

        const uint32_t aBaseS = sb + stg * (STAGE_FLOATS * 4);
        const uint32_t bBaseS = aBaseS + 128 * 32 * 4;
#pragma unroll
        for (int ks = 0; ks < 4; ks++) {
            const uint32_t k0 = (uint32_t)ks * 8;
            const uint32_t kxA = ((k0 + hA) ^ sww) << 2;
            const uint32_t kxB = ((k0 + hB) ^ sww) << 2;
            uint32_t af[4][4], bq[2][4];
#pragma unroll
            for (int mi = 0; mi < 4; mi++)
                ldsm_x4(af[mi], aBaseS + aOff[mi] + kxA);
#pragma unroll
            for (int np = 0; np < 2; np++)
                ldsm_x4(bq[np], bBaseS + bOff[np] + kxB);
#pragma unroll
            for (int mi = 0; mi < 4; mi++)
#pragma unroll
                for (int ni = 0; ni < 4; ni++)
                    mma_tf32(acc[mi][ni], af[mi],
                             bq[ni >> 1][(ni & 1) * 2], bq[ni >> 1][(ni & 1) * 2 + 1]);
        }
        stg = (stg + 1 >= STAGES) ? 0 : (stg + 1);
    }
#undef LOAD_STAGE

    // Epilogue: out = f[b,o]*acc + bias[o] + noise_w[o]*noise
#pragma unroll
    for (int mi = 0; mi < 4; mi++) {
#pragma unroll
        for (int half = 0; half < 2; half++) {
            const int o = m0 + mBase + mi * 16 + r + half * 8;
            const float fo = g_f[b * OC + o];
            const float bo = bias[o];
            const float nw = noise_w[o];
            const size_t base = ((size_t)b * OC + o) * 4096 + hw0 + nBase;
#pragma unroll
            for (int ni = 0; ni < 4; ni++) {
                const size_t off = base + ni * 8 + cq * 2;
                float2 nv = *reinterpret_cast<const float2*>(noise + off);
                const float d0 = acc[mi][ni][half * 2 + 0];
                const float d1 = acc[mi][ni][half * 2 + 1];
                float2 ov;
                ov.x = fmaf(fo, d0, fmaf(nw, nv.x, bo));
                ov.y = fmaf(fo, d1, fmaf(nw, nv.y, bo));
                *reinterpret_cast<float2*>(out + off) = ov;
            }
        }
    }
}

// ---------------------------------------------------------------------------
extern "C" void kernel_launch(void* const* d_in, const int* in_sizes, int n_in,
                              void* d_out, int out_size) {
    const float* x       = (const float*)d_in[0];
    const float* w       = (const float*)d_in[1];
    const float* conv_w  = (const float*)d_in[2];
    const float* lin_w   = (const float*)d_in[3];
    const float* lin_b   = (const float*)d_in[4];
    const float* bias    = (const float*)d_in[5];
    const float* noise_w = (const float*)d_in[6];
    const float* noise   = (const float*)d_in[7];
    float* out = (float*)d_out;

    prep1_kernel<<<BORDER_BLKS + CWR_BLKS + CS_BLKS, 256>>>(conv_w);
    style_kernel<<<(B_ * IC) / 8, 256>>>(w, lin_w, lin_b);
    prep3_kernel<<<4096, 256>>>(x);

    cudaFuncSetAttribute(conv_mma_kernel,
                         cudaFuncAttributeMaxDynamicSharedMemorySize, GEMM_SMEM);
    conv_mma_kernel<<<dim3(4, 1024), 256, GEMM_SMEM>>>(bias, noise_w, noise, out);
}

// round 9
// speedup vs baseline: 15.9109x; 1.8664x over previous
#include <cuda_runtime.h>
#include <cuda_fp16.h>
#include <cstdint>

#define B_    32
#define IC    512
#define OC    512
#define WDIM  512

// ---------------------------------------------------------------------------
// Helpers (base-target PTX only: cp.async + mma.sync + ldmatrix)
// ---------------------------------------------------------------------------
__device__ __forceinline__ uint32_t smem_to_u32(const void* p) {
    uint32_t a;
    asm("{ .reg .u64 t; cvta.to.shared.u64 t, %1; cvt.u32.u64 %0, t; }"
        : "=r"(a) : "l"(p));
    return a;
}

__device__ __forceinline__ void cp_async16(uint32_t s, const void* g) {
    asm volatile("cp.async.cg.shared.global [%0], [%1], 16;" :: "r"(s), "l"(g));
}
__device__ __forceinline__ void cp_commit() {
    asm volatile("cp.async.commit_group;");
}
__device__ __forceinline__ void cp_wait1() {
    asm volatile("cp.async.wait_group 1;" ::: "memory");
}
__device__ __forceinline__ void cp_wait0() {
    asm volatile("cp.async.wait_group 0;" ::: "memory");
}

__device__ __forceinline__ void ldsm_x4(uint32_t* r, uint32_t addr) {
    asm volatile("ldmatrix.sync.aligned.m8n8.x4.shared.b16 {%0,%1,%2,%3}, [%4];"
                 : "=r"(r[0]), "=r"(r[1]), "=r"(r[2]), "=r"(r[3]) : "r"(addr));
}

// fp16 MMA m16n8k16, fp32 accumulate
__device__ __forceinline__ void mma_f16(float* d, const uint32_t* a,
                                        const uint32_t b0, const uint32_t b1) {
    asm volatile(
        "mma.sync.aligned.m16n8k16.row.col.f32.f16.f16.f32 "
        "{%0,%1,%2,%3}, {%4,%5,%6,%7}, {%8,%9}, {%0,%1,%2,%3};"
        : "+f"(d[0]), "+f"(d[1]), "+f"(d[2]), "+f"(d[3])
        : "r"(a[0]), "r"(a[1]), "r"(a[2]), "r"(a[3]), "r"(b0), "r"(b1));
}

// ---------------------------------------------------------------------------
// Scratch
// ---------------------------------------------------------------------------
__device__ float  g_style[B_ * IC];                  // style[b,i] (fp32)
__device__ float  g_cs[OC * IC];                     // s_conv^2 * sum_k cw^2
__device__ float  g_f[B_ * OC];                      // demod factor
__device__ __half g_cwrh[9 * OC * IC];               // [s][o][i]  fp16
__device__ __half g_xsph[(size_t)B_ * 66 * 66 * IC]; // [b][h][w][i] fp16, padded

// ---------------------------------------------------------------------------
// prep1: border zeroing + cwr relayout + cs reduction (fused)
// ---------------------------------------------------------------------------
#define BORDER_BLKS 16640
#define CWR_BLKS    9216
#define CS_BLKS     1024

__global__ void prep1_kernel(const float* __restrict__ cw) {
    const int bid = blockIdx.x;
    if (bid < BORDER_BLKS) {
        const int idx = bid * 256 + threadIdx.x;      // 32*260*512
        const int i = idx & 511;
        const int p = idx >> 9;
        const int b = p / 260;
        const int r = p - b * 260;
        int h, w;
        if (r < 66)       { h = 0;  w = r; }
        else if (r < 132) { h = 65; w = r - 66; }
        else { int r2 = r - 132; h = 1 + (r2 >> 1); w = (r2 & 1) * 65; }
        g_xsph[((size_t)(b * 66 + h) * 66 + w) * IC + i] = __half(0.f);
    } else if (bid < BORDER_BLKS + CWR_BLKS) {
        const int j = (bid - BORDER_BLKS) * 256 + threadIdx.x;  // 9*512*512
        const int s = j >> 18;
        const int rem = j & 262143;
        const int o = rem >> 9, i = rem & 511;
        g_cwrh[j] = __float2half_rn(cw[(size_t)(o * IC + i) * 9 + s]);
    } else {
        const int idx = (bid - BORDER_BLKS - CWR_BLKS) * 256 + threadIdx.x;
        const float* p = cw + (size_t)idx * 9;
        float s = 0.f;
#pragma unroll
        for (int k = 0; k < 9; k++) { float v = p[k]; s += v * v; }
        g_cs[idx] = s * (1.0f / 2304.0f);
    }
}

// ---------------------------------------------------------------------------
// style[b,i] = (w[b,:] . lin_w[i,:]) / 16 + lin_b[i]   (one warp per (b,i))
// ---------------------------------------------------------------------------
__global__ void style_kernel(const float* __restrict__ w,
                             const float* __restrict__ lin_w,
                             const float* __restrict__ lin_b) {
    const int gw  = (blockIdx.x * 256 + threadIdx.x) >> 5;
    const int lid = threadIdx.x & 31;
    const int b = gw >> 9, i = gw & 511;
    const float* wr = w + b * WDIM;
    const float* lw = lin_w + (size_t)i * WDIM;
    float acc = 0.f;
#pragma unroll
    for (int d = 0; d < WDIM / 32; d++)
        acc += wr[d * 32 + lid] * lw[d * 32 + lid];
#pragma unroll
    for (int off = 16; off > 0; off >>= 1)
        acc += __shfl_xor_sync(0xffffffffu, acc, off);
    if (lid == 0) g_style[b * IC + i] = acc * 0.0625f + lin_b[i];
}

// ---------------------------------------------------------------------------
// prep3: xsp transpose+premultiply (blocks [0,2048)) + f demod ([2048,4096))
// ---------------------------------------------------------------------------
__global__ void prep3_kernel(const float* __restrict__ x) {
    if (blockIdx.x < 2048) {
        __shared__ float sm[64][65];
        const int bh = blockIdx.x;
        const int b = bh >> 6, h = bh & 63;
        const int tx = threadIdx.x & 63, ty = threadIdx.x >> 6;
        for (int ic = 0; ic < 8; ic++) {
#pragma unroll
            for (int r = 0; r < 16; r++) {
                const int il = ty + r * 4;
                const int i = ic * 64 + il;
                sm[il][tx] = x[((size_t)(b * IC) + i) * 4096 + h * 64 + tx] *
                             g_style[b * IC + i];
            }
            __syncthreads();
#pragma unroll
            for (int r = 0; r < 16; r++) {
                const int w = ty + r * 4;
                g_xsph[((size_t)(b * 66 + h + 1) * 66 + (w + 1)) * IC + ic * 64 + tx] =
                    __float2half_rn(sm[tx][w]);
            }
            __syncthreads();
        }
    } else {
        const int gw  = ((blockIdx.x - 2048) * 256 + threadIdx.x) >> 5;
        const int lid = threadIdx.x & 31;
        const int b = gw >> 9, o = gw & 511;
        const float* st = g_style + b * IC;
        const float* cs = g_cs + (size_t)o * IC;
        float acc = 0.f;
#pragma unroll
        for (int d = 0; d < IC / 32; d++) {
            float sv = st[d * 32 + lid];
            acc += sv * sv * cs[d * 32 + lid];
        }
#pragma unroll
        for (int off = 16; off > 0; off >>= 1)
            acc += __shfl_xor_sync(0xffffffffu, acc, off);
        if (lid == 0) g_f[b * OC + o] = (1.0f / 48.0f) * rsqrtf(acc + 1e-8f);
    }
}

// ---------------------------------------------------------------------------
// Main GEMM: fp16 mma.sync m16n8k16, 128x128x64 CTA, cp.async 3-stage ring.
// SMEM tiles: [row][64] halfs = 128B/row, 8x16B chunks, chunk^(row&7) swizzle.
// 72 k-chunks = 9 shifts x 8 channel-chunks of 64.
// ---------------------------------------------------------------------------
#define STAGE_BYTES 32768          // A 128*64*2 + B 128*64*2
#define STAGES 3
#define GEMM_SMEM (STAGES * STAGE_BYTES)   // 96 KB

__global__ void __launch_bounds__(256, 2)
conv_mma_kernel(const float* __restrict__ bias, const float* __restrict__ noise_w,
                const float* __restrict__ noise, float* __restrict__ out) {
    extern __shared__ char smc[];
    const uint32_t sb = smem_to_u32(smc);

    const int t   = threadIdx.x;
    const int wid = t >> 5, lid = t & 31;
    const int m0  = blockIdx.x * 128;    // 4 m-blocks fastest -> L2 B-sharing
    const int nt  = blockIdx.y;          // 0..1023
    const int b   = nt >> 5;
    const int h0  = (nt & 31) * 2;
    const int hw0 = (nt & 31) * 128;

    const int wm = wid >> 2, wn = wid & 3;
    const int mBase = wm * 64, nBase = wn * 32;
    const int r = lid >> 2, cq = lid & 3;

    // ldmatrix addressing (m16n8k16 canonical fragment maps)
    const int rowin = lid & 7;
    const int jm = lid >> 3;                         // 0..3
    // A: matrices (rows lo/hi) x (k lo/hi):  jm&1 -> row half, jm>>1 -> k half
    uint32_t aRowB[4], aXor[4];
    {
        const int ar = mBase + ((jm & 1) << 3) + rowin;
#pragma unroll
        for (int mi = 0; mi < 4; mi++) {
            aRowB[mi] = (uint32_t)(ar + mi * 16) * 128u;
            aXor[mi]  = (uint32_t)((ar + mi * 16) & 7);
        }
    }
    const uint32_t aCh = (uint32_t)(jm >> 1);        // k-half select
    // B: matrices (k lo/hi) x (n lo/hi):  jm&1 -> k half, jm>>1 -> n half
    uint32_t bRowB[2], bXor[2];
    {
        const int br = nBase + ((jm >> 1) << 3) + rowin;
#pragma unroll
        for (int np = 0; np < 2; np++) {
            bRowB[np] = (uint32_t)(br + np * 16) * 128u;
            bXor[np]  = (uint32_t)((br + np * 16) & 7);
        }
    }
    const uint32_t bCh = (uint32_t)(jm & 1);         // k-half select

    // loader indices: rows t>>3 (+32 x4), chunk t&7
    const int lrow0 = t >> 3;
    const int lchk  = t & 7;

    float acc[4][4][4];
#pragma unroll
    for (int a = 0; a < 4; a++)
#pragma unroll
        for (int bq2 = 0; bq2 < 4; bq2++)
#pragma unroll
            for (int cc = 0; cc < 4; cc++) acc[a][bq2][cc] = 0.f;

#define LOAD_STAGE(c_, stg_)                                                    \
    do {                                                                        \
        const int s_  = (c_) >> 3;                                              \
        const int kc_ = (c_) & 7;                                               \
        const int kh_ = s_ / 3, kw_ = s_ - kh_ * 3;                             \
        const uint32_t aBase = sb + (stg_) * STAGE_BYTES;                       \
        const uint32_t bBase = aBase + 128 * 128;                               \
        const __half* Ag = g_cwrh + ((size_t)(s_ * OC + m0) * IC) + kc_ * 64 +  \
                           lchk * 8;                                            \
        _Pragma("unroll")                                                       \
        for (int it = 0; it < 4; it++) {                                        \
            const int row = lrow0 + it * 32;                                    \
            const uint32_t dst = aBase + row * 128 +                            \
                                 ((lchk ^ (row & 7)) << 4);                     \
            cp_async16(dst, Ag + (size_t)row * IC);                             \
        }                                                                       \
        _Pragma("unroll")                                                       \
        for (int it = 0; it < 4; it++) {                                        \
            const int row = lrow0 + it * 32;                                    \
            const int hg = h0 + (row >> 6) + kh_;                               \
            const int wg = (row & 63) + kw_;                                    \
            const __half* Bg = g_xsph +                                         \
                ((size_t)((b * 66 + hg) * 66 + wg)) * IC + kc_ * 64 + lchk * 8; \
            const uint32_t dst = bBase + row * 128 +                            \
                                 ((lchk ^ (row & 7)) << 4);                     \
            cp_async16(dst, Bg);                                                \
        }                                                                       \
        cp_commit();                                                            \
    } while (0)

    LOAD_STAGE(0, 0);
    LOAD_STAGE(1, 1);

    int stg = 0;
    for (int c = 0; c < 72; c++) {
        if (c < 71) cp_wait1(); else cp_wait0();
        __syncthreads();
        if (c + 2 < 72) {
            const int stg2 = (stg + 2 >= STAGES) ? (stg + 2 - STAGES) : (stg + 2);
            LOAD_STAGE(c + 2, stg2);
        }

        const uint32_t aBaseS = sb + stg * STAGE_BYTES;
        const uint32_t bBaseS = aBaseS + 128 * 128;
#pragma unroll
        for (int ks = 0; ks < 4; ks++) {
            const uint32_t kA = (uint32_t)(ks << 1) + aCh;
            const uint32_t kB = (uint32_t)(ks << 1) + bCh;
            uint32_t af[4][4], bq[2][4];
#pragma unroll
            for (int mi = 0; mi < 4; mi++)
                ldsm_x4(af[mi], aBaseS + aRowB[mi] + ((kA ^ aXor[mi]) << 4));
#pragma unroll
            for (int np = 0; np < 2; np++)
                ldsm_x4(bq[np], bBaseS + bRowB[np] + ((kB ^ bXor[np]) << 4));
#pragma unroll
            for (int mi = 0; mi < 4; mi++)
#pragma unroll
                for (int ni = 0; ni < 4; ni++)
                    mma_f16(acc[mi][ni], af[mi],
                            bq[ni >> 1][(ni & 1) * 2], bq[ni >> 1][(ni & 1) * 2 + 1]);
        }
        stg = (stg + 1 >= STAGES) ? 0 : (stg + 1);
    }
#undef LOAD_STAGE

    // Epilogue: out = f[b,o]*acc + bias[o] + noise_w[o]*noise
#pragma unroll
    for (int mi = 0; mi < 4; mi++) {
#pragma unroll
        for (int half = 0; half < 2; half++) {
            const int o = m0 + mBase + mi * 16 + r + half * 8;
            const float fo = g_f[b * OC + o];
            const float bo = bias[o];
            const float nw = noise_w[o];
            const size_t base = ((size_t)b * OC + o) * 4096 + hw0 + nBase;
#pragma unroll
            for (int ni = 0; ni < 4; ni++) {
                const size_t off = base + ni * 8 + cq * 2;
                float2 nv = *reinterpret_cast<const float2*>(noise + off);
                const float d0 = acc[mi][ni][half * 2 + 0];
                const float d1 = acc[mi][ni][half * 2 + 1];
                float2 ov;
                ov.x = fmaf(fo, d0, fmaf(nw, nv.x, bo));
                ov.y = fmaf(fo, d1, fmaf(nw, nv.y, bo));
                *reinterpret_cast<float2*>(out + off) = ov;
            }
        }
    }
}

// ---------------------------------------------------------------------------
extern "C" void kernel_launch(void* const* d_in, const int* in_sizes, int n_in,
                              void* d_out, int out_size) {
    const float* x       = (const float*)d_in[0];
    const float* w       = (const float*)d_in[1];
    const float* conv_w  = (const float*)d_in[2];
    const float* lin_w   = (const float*)d_in[3];
    const float* lin_b   = (const float*)d_in[4];
    const float* bias    = (const float*)d_in[5];
    const float* noise_w = (const float*)d_in[6];
    const float* noise   = (const float*)d_in[7];
    float* out = (float*)d_out;

    prep1_kernel<<<BORDER_BLKS + CWR_BLKS + CS_BLKS, 256>>>(conv_w);
    style_kernel<<<(B_ * IC) / 8, 256>>>(w, lin_w, lin_b);
    prep3_kernel<<<4096, 256>>>(x);

    cudaFuncSetAttribute(conv_mma_kernel,
                         cudaFuncAttributeMaxDynamicSharedMemorySize, GEMM_SMEM);
    conv_mma_kernel<<<dim3(4, 1024), 256, GEMM_SMEM>>>(bias, noise_w, noise, out);
}